// round 14
// baseline (speedup 1.0000x reference)
#include <cuda_runtime.h>
#include <math_constants.h>

// Joint bilateral filter, 9x9, sigma_s=2, sigma_r=0.1.  B=16,C=1,H=768,W=1024 fp32.
//
// Sparsity-exploiting: only pixels with sparse != 1.0 contribute (padding value
// 1.0 is also "invalid" -> no reflect handling needed).  ~5% valid -> build
// per-row compact lists of valid entries over the warp's 40-col window
// (warp spans exactly TX=32 centers, window = 32 + 2*4).
//
// Weight identity (ONE exp2 per (center, valid-entry, row)):
//   w_spatial * w_range = 2^( Ks2*(dx^2+dy^2) + K*dp_p^2 - 2K*d0*dp_p ) * 2^(K*d0^2)
// E = 2^(K*d0^2) applied per center in epilogue, recovered from c1 = -2K*d0.
//   K = -50/ln2, Ks2 = -1/(8 ln2).
// |dx|>4 masked arithmetically: bx += max(fdx^2-20.25,0)*(-1e30) -> ex2 -> 0.
// Row counts prefetched one row ahead; list pointer strided; center/out
// addressed via per-thread pointers walked by IMG_W (fewer live index regs,
// enabling 7 CTAs/SM at 36 regs).

#define IMG_H 768
#define IMG_W 1024
#define IMG_B 16

#define TX 32
#define RY 8
#define BDX 32
#define BDY 8                 // 256 threads; each owns RY=8 rows of one column
#define TY (BDY * RY)         // 64
#define HALO 4
#define SW (TX + 2 * HALO)    // 40
#define SH (TY + 2 * HALO)    // 72
#define NROWS (RY + 2 * HALO) // 16

#define KCONST (-72.134752044448170f)    // -50 / ln(2)
#define KS2    (-0.18033688011112042f)   // -1 / (8 ln 2)
#define INV4K  (-0.0034657359027997264f) // 1 / (4*KCONST)
#define CAP 20                           // entries per row list (padded +1 for prefetch)

__device__ __forceinline__ float ex2_fast(float x) {
    float y;
    asm("ex2.approx.ftz.f32 %0, %1;" : "=f"(y) : "f"(x));
    return y;   // ex2(-inf) = +0
}

__global__ void __launch_bounds__(BDX * BDY, 7)
jbf_sparse_kernel(const float* __restrict__ sparse,
                  const float* __restrict__ depth,
                  float* __restrict__ out)
{
    __shared__ float4 s_list[SH][CAP + 1];  // (lx_f, dp, a=K*dp^2, sv); +1 pad for prefetch
    __shared__ int    s_cnt[SH];

    const int x0 = blockIdx.x * TX;
    const int y0 = blockIdx.y * TY;
    const size_t base = (size_t)blockIdx.z * (IMG_H * IMG_W);

    const int tid = threadIdx.y * BDX + threadIdx.x;

    if (tid < SH) s_cnt[tid] = 0;
    __syncthreads();

    // ---- phase 1: scan tile+halo, append valid entries (one list per row) ----
    for (int i = tid; i < SH * SW; i += BDX * BDY) {
        const int ly = i / SW;
        const int lx = i - ly * SW;
        const int gy = y0 + ly - HALO;
        const int gx = x0 + lx - HALO;
        if (gy >= 0 && gy < IMG_H && gx >= 0 && gx < IMG_W) {
            const size_t idx = base + (size_t)gy * IMG_W + gx;
            const float sv = sparse[idx];
            if (sv != 1.0f) {
                const float dp = depth[idx];
                const float a = KCONST * dp * dp;
                int p = atomicAdd(&s_cnt[ly], 1);
                if (p < CAP) s_list[ly][p] = make_float4((float)lx, dp, a, sv);
            }
        }
    }

    // ---- per-center state (pointer-walked center loads) ----
    const int tx = threadIdx.x;
    const int ry0 = threadIdx.y * RY;
    const float fcol = (float)(tx + HALO);

    const size_t cbase = base + (size_t)(y0 + ry0) * IMG_W + (x0 + tx);
    const float* __restrict__ dptr = depth + cbase;

    float c1[RY], num[RY], den[RY];
#pragma unroll
    for (int r = 0; r < RY; r++) {
        const float d0 = dptr[(size_t)r * IMG_W];
        c1[r] = (-2.0f * KCONST) * d0;
        num[r] = 0.0f;
        den[r] = 0.0f;
    }

    __syncthreads();

    // ---- phase 2: gather over valid entries only ----
    const float4* __restrict__ lp = &s_list[ry0][0];
    int n_cur = min(s_cnt[ry0], CAP);
#pragma unroll
    for (int yy = 0; yy < NROWS; yy++) {
        // prefetch next row's count before processing this row's entries
        const int n_next = (yy + 1 < NROWS) ? min(s_cnt[ry0 + yy + 1], CAP) : 0;
        if (n_cur > 0) {
            float4 en = lp[0];
            for (int e = 0; e < n_cur; e++) {
                const float4 nx = lp[e + 1];        // safe: array padded to CAP+1
                const float fdx = en.x - fcol;
                const float d2 = fdx * fdx;
                float bx = fmaf(KS2, d2, en.z);
                // arithmetic window mask: in-window -> +0 exactly; out -> -huge
                bx = fmaf(fmaxf(d2 - 20.25f, 0.0f), -1e30f, bx);
                const float dpv = en.y;
                const float svv = en.w;
#pragma unroll
                for (int r = 0; r < RY; r++) {
                    const int dy = yy - HALO - r;
                    if (dy < -HALO || dy > HALO) continue;
                    const float cdy = KS2 * (float)(dy * dy);   // compile-time
                    const float u = fmaf(c1[r], dpv, bx + cdy);
                    const float rng = ex2_fast(u);              // 0 if masked
                    num[r] = fmaf(rng, svv, num[r]);
                    den[r] += rng;
                }
                en = nx;
            }
        }
        lp += (CAP + 1);
        n_cur = n_next;
    }

    // ---- epilogue: E = 2^(K*d0^2) = 2^(c1^2/(4K)); divide ----
    float* __restrict__ optr = out + cbase;
#pragma unroll
    for (int r = 0; r < RY; r++) {
        const float E = ex2_fast(c1[r] * c1[r] * INV4K);
        const float dent = E * den[r];
        const float numt = E * num[r];
        const float o = (dent < 1e-8f) ? 1.0f : numt / (dent + 1e-8f);
        optr[(size_t)r * IMG_W] = o;
    }
}

extern "C" void kernel_launch(void* const* d_in, const int* in_sizes, int n_in,
                              void* d_out, int out_size)
{
    (void)in_sizes; (void)n_in; (void)out_size;
    const float* sparse = (const float*)d_in[0];
    const float* depth  = (const float*)d_in[1];
    float* out = (float*)d_out;

    dim3 block(BDX, BDY);
    dim3 grid(IMG_W / TX, IMG_H / TY, IMG_B);
    jbf_sparse_kernel<<<grid, block>>>(sparse, depth, out);
}

// round 15
// speedup vs baseline: 1.0840x; 1.0840x over previous
#include <cuda_runtime.h>
#include <math_constants.h>

// Joint bilateral filter, 9x9, sigma_s=2, sigma_r=0.1.  B=16,C=1,H=768,W=1024 fp32.
//
// Sparsity-exploiting: only pixels with sparse != 1.0 contribute (padding value
// 1.0 is also "invalid" -> no reflect handling needed).  ~5% valid -> build
// per-row compact lists of valid entries over the warp's 40-col window
// (warp spans exactly TX=32 centers, window = 32 + 2*4).
//
// Weight identity (ONE exp2 per (center, valid-entry, row)):
//   w_spatial * w_range = 2^( Ks2*(dx^2+dy^2) + K*dp_p^2 - 2K*d0*dp_p ) * 2^(K*d0^2)
// E = 2^(K*d0^2) applied per center in epilogue, recovered from c1 = -2K*d0.
//   K = -50/ln2, Ks2 = -1/(8 ln2).
// |dx|>4 masked arithmetically: bx += max(fdx^2-20.25,0)*(-1e30) -> ex2 -> 0.
// Row counts prefetched one row ahead; list pointer strided; branchless row
// entry loop (empty rows fall through the for-loop).

#define IMG_H 768
#define IMG_W 1024
#define IMG_B 16

#define TX 32
#define RY 8
#define BDX 32
#define BDY 8                 // 256 threads; each owns RY=8 rows of one column
#define TY (BDY * RY)         // 64
#define HALO 4
#define SW (TX + 2 * HALO)    // 40
#define SH (TY + 2 * HALO)    // 72
#define NROWS (RY + 2 * HALO) // 16

#define KCONST (-72.134752044448170f)    // -50 / ln(2)
#define KS2    (-0.18033688011112042f)   // -1 / (8 ln 2)
#define INV4K  (-0.0034657359027997264f) // 1 / (4*KCONST)
#define CAP 20                           // entries per row list (padded +1 for prefetch)

__device__ __forceinline__ float ex2_fast(float x) {
    float y;
    asm("ex2.approx.ftz.f32 %0, %1;" : "=f"(y) : "f"(x));
    return y;   // ex2(-inf) = +0
}

__global__ void __launch_bounds__(BDX * BDY, 6)
jbf_sparse_kernel(const float* __restrict__ sparse,
                  const float* __restrict__ depth,
                  float* __restrict__ out)
{
    __shared__ float4 s_list[SH][CAP + 1];  // (lx_f, dp, a=K*dp^2, sv); +1 pad for prefetch
    __shared__ int    s_cnt[SH];

    const int x0 = blockIdx.x * TX;
    const int y0 = blockIdx.y * TY;
    const size_t base = (size_t)blockIdx.z * (IMG_H * IMG_W);

    const int tid = threadIdx.y * BDX + threadIdx.x;

    if (tid < SH) s_cnt[tid] = 0;
    __syncthreads();

    // ---- phase 1: scan tile+halo, append valid entries (one list per row) ----
    for (int i = tid; i < SH * SW; i += BDX * BDY) {
        const int ly = i / SW;
        const int lx = i - ly * SW;
        const int gy = y0 + ly - HALO;
        const int gx = x0 + lx - HALO;
        if (gy >= 0 && gy < IMG_H && gx >= 0 && gx < IMG_W) {
            const size_t idx = base + (size_t)gy * IMG_W + gx;
            const float sv = sparse[idx];
            if (sv != 1.0f) {
                const float dp = depth[idx];
                const float a = KCONST * dp * dp;
                int p = atomicAdd(&s_cnt[ly], 1);
                if (p < CAP) s_list[ly][p] = make_float4((float)lx, dp, a, sv);
            }
        }
    }

    // ---- per-center state (pointer-walked center loads) ----
    const int tx = threadIdx.x;
    const int ry0 = threadIdx.y * RY;
    const float fcol = (float)(tx + HALO);

    const size_t cbase = base + (size_t)(y0 + ry0) * IMG_W + (x0 + tx);
    const float* __restrict__ dptr = depth + cbase;

    float c1[RY], num[RY], den[RY];
#pragma unroll
    for (int r = 0; r < RY; r++) {
        const float d0 = dptr[(size_t)r * IMG_W];
        c1[r] = (-2.0f * KCONST) * d0;
        num[r] = 0.0f;
        den[r] = 0.0f;
    }

    __syncthreads();

    // ---- phase 2: gather over valid entries only (branchless rows) ----
    const float4* __restrict__ lp = &s_list[ry0][0];
    int n_cur = min(s_cnt[ry0], CAP);
#pragma unroll
    for (int yy = 0; yy < NROWS; yy++) {
        // prefetch next row's count before processing this row's entries
        const int n_next = (yy + 1 < NROWS) ? min(s_cnt[ry0 + yy + 1], CAP) : 0;
        float4 en = lp[0];                      // padded: safe even when n_cur==0
        for (int e = 0; e < n_cur; e++) {
            const float4 nx = lp[e + 1];        // safe: array padded to CAP+1
            const float fdx = en.x - fcol;
            const float d2 = fdx * fdx;
            float bx = fmaf(KS2, d2, en.z);
            // arithmetic window mask: in-window -> +0 exactly; out -> -huge
            bx = fmaf(fmaxf(d2 - 20.25f, 0.0f), -1e30f, bx);
            const float dpv = en.y;
            const float svv = en.w;
#pragma unroll
            for (int r = 0; r < RY; r++) {
                const int dy = yy - HALO - r;
                if (dy < -HALO || dy > HALO) continue;
                const float cdy = KS2 * (float)(dy * dy);   // compile-time
                const float u = fmaf(c1[r], dpv, bx + cdy);
                const float rng = ex2_fast(u);              // 0 if masked
                num[r] = fmaf(rng, svv, num[r]);
                den[r] += rng;
            }
            en = nx;
        }
        lp += (CAP + 1);
        n_cur = n_next;
    }

    // ---- epilogue: E = 2^(K*d0^2) = 2^(c1^2/(4K)); divide ----
    float* __restrict__ optr = out + cbase;
#pragma unroll
    for (int r = 0; r < RY; r++) {
        const float E = ex2_fast(c1[r] * c1[r] * INV4K);
        const float dent = E * den[r];
        const float numt = E * num[r];
        const float o = (dent < 1e-8f) ? 1.0f : numt / (dent + 1e-8f);
        optr[(size_t)r * IMG_W] = o;
    }
}

extern "C" void kernel_launch(void* const* d_in, const int* in_sizes, int n_in,
                              void* d_out, int out_size)
{
    (void)in_sizes; (void)n_in; (void)out_size;
    const float* sparse = (const float*)d_in[0];
    const float* depth  = (const float*)d_in[1];
    float* out = (float*)d_out;

    dim3 block(BDX, BDY);
    dim3 grid(IMG_W / TX, IMG_H / TY, IMG_B);
    jbf_sparse_kernel<<<grid, block>>>(sparse, depth, out);
}

// round 16
// speedup vs baseline: 1.2998x; 1.1991x over previous
#include <cuda_runtime.h>
#include <math_constants.h>

// Joint bilateral filter, 9x9, sigma_s=2, sigma_r=0.1.  B=16,C=1,H=768,W=1024 fp32.
//
// Sparsity-exploiting: only pixels with sparse != 1.0 contribute (padding value
// 1.0 is also "invalid" -> no reflect handling needed).  ~5% valid -> build
// per-row compact lists of valid entries over the warp's 40-col window
// (warp spans exactly TX=32 centers, window = 32 + 2*4).
//
// Weight identity (ONE exp2 per (center, valid-entry, row)):
//   w_spatial * w_range = 2^( Ks2*(dx^2+dy^2) + K*dp_p^2 - 2K*d0*dp_p ) * 2^(K*d0^2)
// E = 2^(K*d0^2) applied per center in epilogue, recovered from c1 = -2K*d0.
//   K = -50/ln2, Ks2 = -1/(8 ln2).
// |dx|>4 masked arithmetically: bx += max(fdx^2-20.25,0)*(-1e30) -> ex2 -> 0.
// Phase 1 scans sparse via float4 quads (rows 16B-aligned since x0 % 32 == 0).
// Row counts prefetched one row ahead; list pointer strided; branchless rows.

#define IMG_H 768
#define IMG_W 1024
#define IMG_B 16

#define TX 32
#define RY 8
#define BDX 32
#define BDY 8                 // 256 threads; each owns RY=8 rows of one column
#define TY (BDY * RY)         // 64
#define HALO 4
#define SW (TX + 2 * HALO)    // 40
#define SH (TY + 2 * HALO)    // 72
#define NROWS (RY + 2 * HALO) // 16
#define QPR (SW / 4)          // 10 quads per tile row

#define KCONST (-72.134752044448170f)    // -50 / ln(2)
#define KS2    (-0.18033688011112042f)   // -1 / (8 ln 2)
#define INV4K  (-0.0034657359027997264f) // 1 / (4*KCONST)
#define CAP 20                           // entries per row list (padded +1 for prefetch)

__device__ __forceinline__ float ex2_fast(float x) {
    float y;
    asm("ex2.approx.ftz.f32 %0, %1;" : "=f"(y) : "f"(x));
    return y;   // ex2(-inf) = +0
}

__global__ void __launch_bounds__(BDX * BDY, 6)
jbf_sparse_kernel(const float* __restrict__ sparse,
                  const float* __restrict__ depth,
                  float* __restrict__ out)
{
    __shared__ float4 s_list[SH][CAP + 1];  // (lx_f, dp, a=K*dp^2, sv); +1 pad for prefetch
    __shared__ int    s_cnt[SH];

    const int x0 = blockIdx.x * TX;
    const int y0 = blockIdx.y * TY;
    const size_t base = (size_t)blockIdx.z * (IMG_H * IMG_W);

    const int tid = threadIdx.y * BDX + threadIdx.x;

    if (tid < SH) s_cnt[tid] = 0;
    __syncthreads();

    // ---- phase 1: scan tile+halo by float4 quads, append valid entries ----
    for (int q = tid; q < SH * QPR; q += BDX * BDY) {
        const int ly = q / QPR;
        const int qx = q - ly * QPR;
        const int gy = y0 + ly - HALO;
        if (gy < 0 || gy >= IMG_H) continue;
        const size_t rowb = base + (size_t)gy * IMG_W;
        const int gxq = x0 + qx * 4 - HALO;      // 16B-aligned (x0 % 32 == 0)
        if (gxq >= 0 && gxq + 3 < IMG_W) {
            // vector path (common)
            const float4 sv4 = *reinterpret_cast<const float4*>(sparse + rowb + gxq);
            const float svs[4] = {sv4.x, sv4.y, sv4.z, sv4.w};
#pragma unroll
            for (int j = 0; j < 4; j++) {
                const float sv = svs[j];
                if (sv != 1.0f) {
                    const float dp = depth[rowb + gxq + j];
                    int p = atomicAdd(&s_cnt[ly], 1);
                    if (p < CAP)
                        s_list[ly][p] = make_float4((float)(qx * 4 + j), dp,
                                                    KCONST * dp * dp, sv);
                }
            }
        } else {
            // edge path (image borders only)
#pragma unroll
            for (int j = 0; j < 4; j++) {
                const int gx = gxq + j;
                if (gx < 0 || gx >= IMG_W) continue;
                const float sv = sparse[rowb + gx];
                if (sv != 1.0f) {
                    const float dp = depth[rowb + gx];
                    int p = atomicAdd(&s_cnt[ly], 1);
                    if (p < CAP)
                        s_list[ly][p] = make_float4((float)(qx * 4 + j), dp,
                                                    KCONST * dp * dp, sv);
                }
            }
        }
    }

    // ---- per-center state (pointer-walked center loads) ----
    const int tx = threadIdx.x;
    const int ry0 = threadIdx.y * RY;
    const float fcol = (float)(tx + HALO);

    const size_t cbase = base + (size_t)(y0 + ry0) * IMG_W + (x0 + tx);
    const float* __restrict__ dptr = depth + cbase;

    float c1[RY], num[RY], den[RY];
#pragma unroll
    for (int r = 0; r < RY; r++) {
        const float d0 = dptr[(size_t)r * IMG_W];
        c1[r] = (-2.0f * KCONST) * d0;
        num[r] = 0.0f;
        den[r] = 0.0f;
    }

    __syncthreads();

    // ---- phase 2: gather over valid entries only (branchless rows) ----
    const float4* __restrict__ lp = &s_list[ry0][0];
    int n_cur = min(s_cnt[ry0], CAP);
#pragma unroll
    for (int yy = 0; yy < NROWS; yy++) {
        // prefetch next row's count before processing this row's entries
        const int n_next = (yy + 1 < NROWS) ? min(s_cnt[ry0 + yy + 1], CAP) : 0;
        float4 en = lp[0];                      // padded: safe even when n_cur==0
        for (int e = 0; e < n_cur; e++) {
            const float4 nx = lp[e + 1];        // safe: array padded to CAP+1
            const float fdx = en.x - fcol;
            const float d2 = fdx * fdx;
            float bx = fmaf(KS2, d2, en.z);
            // arithmetic window mask: in-window -> +0 exactly; out -> -huge
            bx = fmaf(fmaxf(d2 - 20.25f, 0.0f), -1e30f, bx);
            const float dpv = en.y;
            const float svv = en.w;
#pragma unroll
            for (int r = 0; r < RY; r++) {
                const int dy = yy - HALO - r;
                if (dy < -HALO || dy > HALO) continue;
                const float cdy = KS2 * (float)(dy * dy);   // compile-time
                const float u = fmaf(c1[r], dpv, bx + cdy);
                const float rng = ex2_fast(u);              // 0 if masked
                num[r] = fmaf(rng, svv, num[r]);
                den[r] += rng;
            }
            en = nx;
        }
        lp += (CAP + 1);
        n_cur = n_next;
    }

    // ---- epilogue: E = 2^(K*d0^2) = 2^(c1^2/(4K)); fast divide ----
    float* __restrict__ optr = out + cbase;
#pragma unroll
    for (int r = 0; r < RY; r++) {
        const float E = ex2_fast(c1[r] * c1[r] * INV4K);
        const float dent = E * den[r];
        const float numt = E * num[r];
        const float o = (dent < 1e-8f) ? 1.0f : __fdividef(numt, dent + 1e-8f);
        optr[(size_t)r * IMG_W] = o;
    }
}

extern "C" void kernel_launch(void* const* d_in, const int* in_sizes, int n_in,
                              void* d_out, int out_size)
{
    (void)in_sizes; (void)n_in; (void)out_size;
    const float* sparse = (const float*)d_in[0];
    const float* depth  = (const float*)d_in[1];
    float* out = (float*)d_out;

    dim3 block(BDX, BDY);
    dim3 grid(IMG_W / TX, IMG_H / TY, IMG_B);
    jbf_sparse_kernel<<<grid, block>>>(sparse, depth, out);
}